// round 17
// baseline (speedup 1.0000x reference)
#include <cuda_runtime.h>
#include <cuda_fp16.h>
#include <cstdint>

// Submanifold sparse conv: rulebook gather -> per-offset 16x16 GEMV -> scatter-add.
// Tensor-core (m16n8k16) warp kernel, column-interleaved so each lane REDs one
// contiguous float4 per rule-row (instruction-floor scatter). R16: coalesced
// index loads (2 LDG.32 per 32 rules instead of 8 redundant ones) with SHFL
// distribution, and 4 blocks/SM occupancy.

constexpr int KOFF = 27;
constexpr int CIN  = 16;
constexpr int COUT = 16;
constexpr int IT   = 4;                  // 32-rule iterations per warp
constexpr int RPW  = 32 * IT;            // rules per warp = 128
constexpr int RPB  = 8 * RPW;            // rules per block = 1024
constexpr int NMAX = 500000;

// fp16 feature scratch, fragment-permuted rows: half order per row =
// [0,1,8,9, 2,3,10,11, 4,5,12,13, 6,7,14,15]  (lane m reads uint2 at m*8B:
// .x = cols {2m,2m+1} -> a0/a1, .y = cols {8+2m,8+2m+1} -> a2/a3)
__device__ __align__(16) __half g_feat_h[NMAX * CIN];

__device__ __forceinline__ unsigned packh2(float lo, float hi) {
    __half2 h = __floats2half2_rn(lo, hi);
    return *reinterpret_cast<unsigned*>(&h);
}

// Fused prologue: permuted f32->f16 feature convert + bias broadcast.
__global__ void prologue_kernel(const float4* __restrict__ feat4,
                                float4* __restrict__ out4,
                                const float4* __restrict__ bias4,
                                int N) {
    const int i = blockIdx.x * blockDim.x + threadIdx.x;
    if (i >= N) return;
    const float4 a = feat4[i * 4 + 0];   // cols 0-3
    const float4 b = feat4[i * 4 + 1];   // cols 4-7
    const float4 c = feat4[i * 4 + 2];   // cols 8-11
    const float4 d = feat4[i * 4 + 3];   // cols 12-15
    uint4 lo, hi;
    lo.x = packh2(a.x, a.y);  lo.y = packh2(c.x, c.y);   // [0,1, 8,9]
    lo.z = packh2(a.z, a.w);  lo.w = packh2(c.z, c.w);   // [2,3, 10,11]
    hi.x = packh2(b.x, b.y);  hi.y = packh2(d.x, d.y);   // [4,5, 12,13]
    hi.z = packh2(b.z, b.w);  hi.w = packh2(d.z, d.w);   // [6,7, 14,15]
    reinterpret_cast<uint4*>(g_feat_h)[i * 2 + 0] = lo;
    reinterpret_cast<uint4*>(g_feat_h)[i * 2 + 1] = hi;

    const float4 b0 = bias4[0], b1 = bias4[1], b2 = bias4[2], b3 = bias4[3];
    out4[i * 4 + 0] = b0;  out4[i * 4 + 1] = b1;
    out4[i * 4 + 2] = b2;  out4[i * 4 + 3] = b3;
}

__device__ __forceinline__ void mma16816(float d[4],
                                         unsigned a0, unsigned a1,
                                         unsigned a2, unsigned a3,
                                         unsigned b0, unsigned b1) {
    asm volatile(
        "mma.sync.aligned.m16n8k16.row.col.f32.f16.f16.f32 "
        "{%0,%1,%2,%3}, {%4,%5,%6,%7}, {%8,%9}, {%0,%1,%2,%3};"
        : "+f"(d[0]), "+f"(d[1]), "+f"(d[2]), "+f"(d[3])
        : "r"(a0), "r"(a1), "r"(a2), "r"(a3), "r"(b0), "r"(b1));
}

__device__ __forceinline__ void red4(float* p, float x, float y, float z, float w) {
    asm volatile("red.global.add.v4.f32 [%0], {%1,%2,%3,%4};"
                 :: "l"(p), "f"(x), "f"(y), "f"(z), "f"(w) : "memory");
}

__global__ void __launch_bounds__(256, 4)
subconv_kernel(const float* __restrict__ weight,   // [27*256] : [k][cin][cout]
               const int*   __restrict__ rin,      // [27*R]
               const int*   __restrict__ rout,     // [27*R]
               float*       __restrict__ out,      // [N*16]
               int R) {
    __shared__ float wsh[CIN * COUT];

    const int k = blockIdx.y;
    wsh[threadIdx.x] = weight[k * (CIN * COUT) + threadIdx.x];
    __syncthreads();

    const int lane = threadIdx.x & 31;
    const int warp = threadIdx.x >> 5;
    const int g    = lane >> 2;   // groupID: rule row within 16-rule tile
    const int m    = lane & 3;    // k-pair / col selector

    // B fragments (built once per warp, reused for 128 rules).
    // Column interleaving: MMA-even's n-column j = output col 2j, MMA-odd's = 2j+1,
    // so lane (g,m) D values are outputs 4m..4m+3 (contiguous float4).
    const unsigned b0e = packh2(wsh[(2 * m)     * 16 + 2 * g],     wsh[(2 * m + 1) * 16 + 2 * g]);
    const unsigned b1e = packh2(wsh[(8 + 2 * m) * 16 + 2 * g],     wsh[(9 + 2 * m) * 16 + 2 * g]);
    const unsigned b0o = packh2(wsh[(2 * m)     * 16 + 2 * g + 1], wsh[(2 * m + 1) * 16 + 2 * g + 1]);
    const unsigned b1o = packh2(wsh[(8 + 2 * m) * 16 + 2 * g + 1], wsh[(9 + 2 * m) * 16 + 2 * g + 1]);

    const int kbase = k * R;                       // <= 6.75M, int32 safe
    const int rb0   = blockIdx.x * RPB + warp * RPW;
    const uint2* __restrict__ fh = reinterpret_cast<const uint2*>(g_feat_h);

    // ---- coalesced index loads for iteration 0: lane holds position rb0+lane ----
    int rin_v, rout_v;
    {
        const int p = rb0 + lane;
        const int c = (p < R) ? p : 0;
        rin_v  = rin[kbase + c];
        rout_v = rout[kbase + c];
    }

#pragma unroll
    for (int it = 0; it < IT; ++it) {
        const int base_it = rb0 + it * 32;

        // ---- distribute indices within the warp (replaces 8 redundant LDGs) ----
        // group u rows: positions base_it + u*16 + g (lo) and +8 (hi)
        const int ilo0 = __shfl_sync(0xffffffffu, rin_v,  g);
        const int ihi0 = __shfl_sync(0xffffffffu, rin_v,  g + 8);
        const int ilo1 = __shfl_sync(0xffffffffu, rin_v,  g + 16);
        const int ihi1 = __shfl_sync(0xffffffffu, rin_v,  g + 24);
        const int olo0 = __shfl_sync(0xffffffffu, rout_v, g);
        const int ohi0 = __shfl_sync(0xffffffffu, rout_v, g + 8);
        const int olo1 = __shfl_sync(0xffffffffu, rout_v, g + 16);
        const int ohi1 = __shfl_sync(0xffffffffu, rout_v, g + 24);

        // ---- gathers (LDG.64; 4 lanes cover one 32B permuted row) ----
        const uint2 alo0 = fh[ilo0 * 4 + m];
        const uint2 ahi0 = fh[ihi0 * 4 + m];
        const uint2 alo1 = fh[ilo1 * 4 + m];
        const uint2 ahi1 = fh[ihi1 * 4 + m];

        // ---- coalesced prefetch of next iteration's indices ----
        if (it + 1 < IT) {
            const int p = base_it + 32 + lane;
            const int c = (p < R) ? p : 0;
            rin_v  = rin[kbase + c];
            rout_v = rout[kbase + c];
        }

        // ---- MMA + scatter, group u = 0 ----
        {
            float de[4] = {0.f, 0.f, 0.f, 0.f};
            float dn[4] = {0.f, 0.f, 0.f, 0.f};
            mma16816(de, alo0.x, ahi0.x, alo0.y, ahi0.y, b0e, b1e);
            mma16816(dn, alo0.x, ahi0.x, alo0.y, ahi0.y, b0o, b1o);
            const int rl = base_it + g;
            if (rl < R) {
                red4(out + (long)olo0 * COUT + 4 * m, de[0], dn[0], de[1], dn[1]);
            }
            if (rl + 8 < R) {
                red4(out + (long)ohi0 * COUT + 4 * m, de[2], dn[2], de[3], dn[3]);
            }
        }
        // ---- MMA + scatter, group u = 1 ----
        {
            float de[4] = {0.f, 0.f, 0.f, 0.f};
            float dn[4] = {0.f, 0.f, 0.f, 0.f};
            mma16816(de, alo1.x, ahi1.x, alo1.y, ahi1.y, b0e, b1e);
            mma16816(dn, alo1.x, ahi1.x, alo1.y, ahi1.y, b0o, b1o);
            const int rl = base_it + 16 + g;
            if (rl < R) {
                red4(out + (long)olo1 * COUT + 4 * m, de[0], dn[0], de[1], dn[1]);
            }
            if (rl + 8 < R) {
                red4(out + (long)ohi1 * COUT + 4 * m, de[2], dn[2], de[3], dn[3]);
            }
        }
    }
}

extern "C" void kernel_launch(void* const* d_in, const int* in_sizes, int n_in,
                              void* d_out, int out_size) {
    const float* features = (const float*)d_in[0];   // [N*16]
    const float* weight   = (const float*)d_in[1];   // [27*16*16]
    const float* bias     = (const float*)d_in[2];   // [16]
    const int*   rules_in = (const int*)d_in[3];     // [27*R]
    const int*   rules_out= (const int*)d_in[4];     // [27*R]
    float* out = (float*)d_out;                      // [N*16]

    const int N = in_sizes[0] / CIN;
    const int R = in_sizes[3] / KOFF;

    // 0) fused prologue: permuted f16 features + bias broadcast
    {
        const int threads = 256;
        const int blocks = (N + threads - 1) / threads;
        prologue_kernel<<<blocks, threads>>>(
            reinterpret_cast<const float4*>(features),
            (float4*)out, (const float4*)bias, N);
    }

    // 1) gather -> MMA -> scatter-add; 1024 rules per block
    {
        const int threads = 256;
        dim3 grid((R + RPB - 1) / RPB, KOFF);
        subconv_kernel<<<grid, threads>>>(
            weight, rules_in, rules_out, out, R);
    }
}